// round 15
// baseline (speedup 1.0000x reference)
#include <cuda_runtime.h>

// Sampler_8658654069314: temperature sampling, B=256 rows, V=128000 vocab.
// Greedy rows (t==0): argmax(logits). Sampled rows: Gumbel-max over logits/t
// with JAX threefry2x32 partitionable-mode PRNG, key (0, 42), fold out0^out1.
// Output dtype is float32 (token values < 2^24, exactly representable).
//
// R15:
//  - Rotates forced onto the FMA pipe: multipliers 2^r live in __constant__
//    memory, rotate = mul.wide.u32 (IMAD.WIDE, reg-pair) + one fused
//    (lo|hi)^x0 LOP3. ptxas cannot strength-reduce an LDC-loaded multiplier
//    back into SHF (which is what killed the R14 attempt).
//  - Single fused kernel: last-arriving segment block per row does the final
//    row argmax (threadfence + atomic counter, deterministic, resets counter
//    for graph replay). Removes the 4.4us second launch and guarantees ncu
//    captures the main kernel.

#define NB   256
#define NV   128000
#define SEG  25
#define COLS (NV / SEG)            // 5120
#define TPB  256
#define NITER (COLS / (TPB * 4))   // 5 float4 iterations per thread

// Deterministic partial-argmax scratch (no device allocation allowed).
__device__ float g_pval[NB * SEG];
__device__ int   g_pidx[NB * SEG];
__device__ int   g_cnt[NB];        // zero-initialized; last block resets to 0

// Rotation amounts as wide-multiply constants. Loaded via LDC at runtime so
// ptxas emits IMAD.WIDE (fma pipe) instead of strength-reducing to SHF (alu).
__constant__ unsigned c_rm[8] = {
    1u << 13, 1u << 15, 1u << 26, 1u << 6,
    1u << 17, 1u << 29, 1u << 16, 1u << 24
};

// rotl(x, r) = lo32(x * 2^r) | hi32(x * 2^r)
__device__ __forceinline__ unsigned rot_mul(unsigned x, unsigned mul) {
    unsigned long long w;
    asm("mul.wide.u32 %0, %1, %2;" : "=l"(w) : "r"(x), "r"(mul));
    return (unsigned)w | (unsigned)(w >> 32);
}

// threefry2x32, key = (0, 42), counter = (hi=0, lo=ctr), 20 rounds.
// Partitionable-mode 32-bit draw = out0 ^ out1.
// ks0 = 0, ks1 = 42, ks2 = 0x1BD11BDA ^ 42 = 0x1BD11BF0.
__device__ __forceinline__ unsigned threefry_fold(unsigned ctr, const unsigned* rm) {
    const unsigned ks1 = 42u;
    const unsigned ks2 = 0x1BD11BF0u;
    unsigned x0 = 0u;             // 0 + ks0
    unsigned x1 = ctr + ks1;      // ctr + ks1
#define TF_R(j) { x0 += x1; x1 = rot_mul(x1, rm[j]) ^ x0; }
    TF_R(0) TF_R(1) TF_R(2) TF_R(3)
    x0 += ks1; x1 += ks2 + 1u;
    TF_R(4) TF_R(5) TF_R(6) TF_R(7)
    x0 += ks2; x1 += 2u;                 // + ks0 + 2
    TF_R(0) TF_R(1) TF_R(2) TF_R(3)
    /* x0 += ks0 (0) */ x1 += ks1 + 3u;
    TF_R(4) TF_R(5) TF_R(6) TF_R(7)
    x0 += ks1; x1 += ks2 + 4u;
    TF_R(0) TF_R(1) TF_R(2) TF_R(3)
    x0 += ks2; x1 += 5u;                 // + ks0 + 5
#undef TF_R
    return x0 ^ x1;
}

// Accurate log(u) for u in [2^-126, 1). Cephes-style: relative-accurate near
// u->1 (critical: -log(u) can be ~1e-7 for the Gumbel winner). Branch-free,
// independent of --use_fast_math. Mostly FFMA (fma pipe).
__device__ __forceinline__ float log_accurate(float u) {
    int   ib = __float_as_int(u);
    int   e  = (ib >> 23) - 126;                              // u = m * 2^e, m in [0.5,1)
    float m  = __int_as_float((ib & 0x007FFFFF) | 0x3F000000);
    bool  sm = m < 0.70710678f;
    float x  = sm ? fmaf(2.0f, m, -1.0f) : (m - 1.0f);        // exact in both branches
    e -= (int)sm;

    float z = x * x;
    float p =              7.0376836292e-2f;
    p = fmaf(p, x, -1.1514610310e-1f);
    p = fmaf(p, x,  1.1676998740e-1f);
    p = fmaf(p, x, -1.2420140846e-1f);
    p = fmaf(p, x,  1.4249322787e-1f);
    p = fmaf(p, x, -1.6668057665e-1f);
    p = fmaf(p, x,  2.0000714765e-1f);
    p = fmaf(p, x, -2.4999993993e-1f);
    p = fmaf(p, x,  3.3333331174e-1f);
    float fe = (float)e;
    float y  = x * z * p;                     // x^3 * P(x)
    y = fmaf(fe, -2.12194440e-4f, y);         // + e * ln2_lo
    y = fmaf(-0.5f, z, y);                    // - x^2/2
    float r = x + y;
    r = fmaf(fe, 0.693359375f, r);            // + e * ln2_hi (exact product)
    return r;
}

__device__ __forceinline__ float gumbel32(unsigned bits) {
    // JAX uniform: u0 = bitcast(bits>>9 | 0x3f800000) - 1; u = max(u0, tiny)
    float u0 = __uint_as_float((bits >> 9) | 0x3F800000u) - 1.0f;
    float u  = fmaxf(u0, 1.17549435e-38f);
    float w  = -log_accurate(u);              // relative-accurate where it matters
    return -__logf(w);                        // MUFU.LG2 path: 4e-6 abs err, harmless
}

__global__ void __launch_bounds__(TPB)
sampler_main(const float* __restrict__ logits, const float* __restrict__ temps,
             float* __restrict__ out) {
    const int row = blockIdx.y;
    const int seg = blockIdx.x;
    const int tid = threadIdx.x;
    const float t = temps[row];
    const float* p = logits + (size_t)row * NV + (size_t)seg * COLS;

    // Hoist the rotate multipliers (warp-uniform LDC -> UR registers).
    unsigned rm[8];
#pragma unroll
    for (int j = 0; j < 8; ++j) rm[j] = c_rm[j];

    float best = __int_as_float(0xff800000);  // -inf
    int   bidx = NV;

    if (t == 0.0f) {
        // Greedy: argmax of raw logits (first occurrence wins).
#pragma unroll 1
        for (int it = 0; it < NITER; ++it) {
            int c = (it * TPB + tid) * 4;
            float4 x = *reinterpret_cast<const float4*>(p + c);
            float v[4] = {x.x, x.y, x.z, x.w};
#pragma unroll
            for (int k = 0; k < 4; ++k) {
                if (v[k] > best) { best = v[k]; bidx = seg * COLS + c + k; }
            }
        }
    } else {
        const float invT = 1.0f / t;
        const unsigned ibase = (unsigned)row * (unsigned)NV + (unsigned)(seg * COLS);
#pragma unroll 1
        for (int it = 0; it < NITER; ++it) {
            int c = (it * TPB + tid) * 4;
            float4 x = *reinterpret_cast<const float4*>(p + c);
            unsigned bits[4];
#pragma unroll
            for (int k = 0; k < 4; ++k) bits[k] = threefry_fold(ibase + (unsigned)(c + k), rm);
            float xv[4] = {x.x, x.y, x.z, x.w};
#pragma unroll
            for (int k = 0; k < 4; ++k) {
                float g = gumbel32(bits[k]);
                float v = fmaf(xv[k], invT, g);
                if (v > best) { best = v; bidx = seg * COLS + c + k; }
            }
        }
    }

    // Block-level argmax reduction (tie-break: smaller index).
    __shared__ float sv[TPB];
    __shared__ int   si[TPB];
    __shared__ int   s_last;
    sv[tid] = best; si[tid] = bidx;
    __syncthreads();
#pragma unroll
    for (int s = TPB / 2; s > 0; s >>= 1) {
        if (tid < s) {
            float v2 = sv[tid + s]; int i2 = si[tid + s];
            float v1 = sv[tid];     int i1 = si[tid];
            if (v2 > v1 || (v2 == v1 && i2 < i1)) { sv[tid] = v2; si[tid] = i2; }
        }
        __syncthreads();
    }
    if (tid == 0) {
        g_pval[row * SEG + seg] = sv[0];
        g_pidx[row * SEG + seg] = si[0];
        __threadfence();
        int prev = atomicAdd(&g_cnt[row], 1);
        s_last = (prev == SEG - 1);
    }
    __syncthreads();

    // Last-arriving block for this row does the final 25-way argmax.
    if (s_last && tid < 32) {
        __threadfence();  // acquire: partials from all segments are visible
        float v = __int_as_float(0xff800000);
        int   i = NV;
        if (tid < SEG) {
            v = g_pval[row * SEG + tid];
            i = g_pidx[row * SEG + tid];
        }
#pragma unroll
        for (int s = 16; s > 0; s >>= 1) {
            float v2 = __shfl_down_sync(0xFFFFFFFFu, v, s);
            int   i2 = __shfl_down_sync(0xFFFFFFFFu, i, s);
            if (v2 > v || (v2 == v && i2 < i)) { v = v2; i = i2; }
        }
        if (tid == 0) {
            out[row] = (float)i;   // float32 output: tokens < 2^24 exact
            g_cnt[row] = 0;        // reset for next graph replay
        }
    }
}

extern "C" void kernel_launch(void* const* d_in, const int* in_sizes, int n_in,
                              void* d_out, int out_size) {
    const float* logits = (const float*)d_in[0];   // [256, 128000] f32
    const float* temps  = (const float*)d_in[1];   // [256] f32
    (void)in_sizes; (void)n_in; (void)out_size;

    dim3 grid(SEG, NB);
    sampler_main<<<grid, TPB>>>(logits, temps, (float*)d_out);
}

// round 16
// speedup vs baseline: 1.2063x; 1.2063x over previous
#include <cuda_runtime.h>

// Sampler_8658654069314: temperature sampling, B=256 rows, V=128000 vocab.
// Greedy rows (t==0): argmax(logits). Sampled rows: Gumbel-max over logits/t
// with JAX threefry2x32 partitionable-mode PRNG, key (0, 42), fold out0^out1.
// Output dtype is float32 (token values < 2^24, exactly representable).
//
// R16: pipe-balance via single-register IMAD, not IMAD.WIDE (R15 showed wide
// ops cost ~2 issue slots). Every threefry add 'x0 += x1' becomes
// mad.lo.u32(x1, one, x0) on the FMA pipe, with 'one' loaded from __constant__
// so ptxas cannot strength-reduce it back to IADD3 (alu). Rotates stay SHF.
// Per round: IMAD(fma) + SHF(alu) + LOP3(alu) -> alu ~50/elem, fma ~50/elem.
// Fused single-kernel final reduce (validated in R15) retained.

#define NB   256
#define NV   128000
#define SEG  25
#define COLS (NV / SEG)            // 5120
#define TPB  256
#define NITER (COLS / (TPB * 4))   // 5 float4 iterations per thread

// Deterministic partial-argmax scratch (no device allocation allowed).
__device__ float g_pval[NB * SEG];
__device__ int   g_pidx[NB * SEG];
__device__ int   g_cnt[NB];        // zero-init; last block resets to 0

// Opaque 1: forces integer adds onto the FMA pipe as IMAD.
__constant__ unsigned c_one = 1u;

// a + b on the FMA pipe: mad.lo.u32(a, one, b). Single-register IMAD, rt=2.
__device__ __forceinline__ unsigned add_fma(unsigned a, unsigned b, unsigned one) {
    unsigned r;
    asm("mad.lo.u32 %0, %1, %2, %3;" : "=r"(r) : "r"(a), "r"(one), "r"(b));
    return r;
}

// threefry2x32, key = (0, 42), counter = (hi=0, lo=ctr), 20 rounds.
// Partitionable-mode 32-bit draw = out0 ^ out1.
// ks0 = 0, ks1 = 42, ks2 = 0x1BD11BDA ^ 42 = 0x1BD11BF0.
__device__ __forceinline__ unsigned threefry_fold(unsigned ctr, unsigned one,
                                                  unsigned ks1r, unsigned ks2r) {
    unsigned x0 = 0u;             // 0 + ks0
    unsigned x1 = ctr + 42u;      // ctr + ks1
    // Round: x0 += x1 (IMAD, fma pipe); x1 = rotl(x1,r) ^ x0 (SHF+LOP3, alu).
#define TF_R(r) { x0 = add_fma(x1, x0, one); \
                  x1 = __funnelshift_l(x1, x1, (r)) ^ x0; }
    TF_R(13) TF_R(15) TF_R(26) TF_R(6)
    x0 = add_fma(ks1r, x0, one); x1 += 0x1BD11BF0u + 1u;   // + ks2 + 1
    TF_R(17) TF_R(29) TF_R(16) TF_R(24)
    x0 = add_fma(ks2r, x0, one); x1 += 2u;                 // + ks0 + 2
    TF_R(13) TF_R(15) TF_R(26) TF_R(6)
    /* x0 += ks0 == 0 */         x1 += 42u + 3u;           // + ks1 + 3
    TF_R(17) TF_R(29) TF_R(16) TF_R(24)
    x0 = add_fma(ks1r, x0, one); x1 += 0x1BD11BF0u + 4u;   // + ks2 + 4
    TF_R(13) TF_R(15) TF_R(26) TF_R(6)
    x0 = add_fma(ks2r, x0, one); x1 += 5u;                 // + ks0 + 5
#undef TF_R
    return x0 ^ x1;
}

// Accurate log(u) for u in [2^-126, 1). Cephes-style: relative-accurate near
// u->1 (critical: -log(u) can be ~1e-7 for the Gumbel winner). Branch-free,
// independent of --use_fast_math. Mostly FFMA (fma pipe).
__device__ __forceinline__ float log_accurate(float u) {
    int   ib = __float_as_int(u);
    int   e  = (ib >> 23) - 126;                              // u = m * 2^e, m in [0.5,1)
    float m  = __int_as_float((ib & 0x007FFFFF) | 0x3F000000);
    bool  sm = m < 0.70710678f;
    float x  = sm ? fmaf(2.0f, m, -1.0f) : (m - 1.0f);        // exact in both branches
    e -= (int)sm;

    float z = x * x;
    float p =              7.0376836292e-2f;
    p = fmaf(p, x, -1.1514610310e-1f);
    p = fmaf(p, x,  1.1676998740e-1f);
    p = fmaf(p, x, -1.2420140846e-1f);
    p = fmaf(p, x,  1.4249322787e-1f);
    p = fmaf(p, x, -1.6668057665e-1f);
    p = fmaf(p, x,  2.0000714765e-1f);
    p = fmaf(p, x, -2.4999993993e-1f);
    p = fmaf(p, x,  3.3333331174e-1f);
    float fe = (float)e;
    float y  = x * z * p;                     // x^3 * P(x)
    y = fmaf(fe, -2.12194440e-4f, y);         // + e * ln2_lo
    y = fmaf(-0.5f, z, y);                    // - x^2/2
    float r = x + y;
    r = fmaf(fe, 0.693359375f, r);            // + e * ln2_hi (exact product)
    return r;
}

__device__ __forceinline__ float gumbel32(unsigned bits) {
    // JAX uniform: u0 = bitcast(bits>>9 | 0x3f800000) - 1; u = max(u0, tiny)
    float u0 = __uint_as_float((bits >> 9) | 0x3F800000u) - 1.0f;
    float u  = fmaxf(u0, 1.17549435e-38f);
    float w  = -log_accurate(u);              // relative-accurate where it matters
    return -__logf(w);                        // MUFU.LG2 path: 4e-6 abs err, harmless
}

__global__ void __launch_bounds__(TPB)
sampler_main(const float* __restrict__ logits, const float* __restrict__ temps,
             float* __restrict__ out) {
    const int row = blockIdx.y;
    const int seg = blockIdx.x;
    const int tid = threadIdx.x;
    const float t = temps[row];
    const float* p = logits + (size_t)row * NV + (size_t)seg * COLS;

    const unsigned one  = c_one;          // opaque 1 (LDC, hoisted)
    const unsigned ks1r = 42u * one;      // keep in registers for add_fma
    const unsigned ks2r = 0x1BD11BF0u * one;

    float best = __int_as_float(0xff800000);  // -inf
    int   bidx = NV;

    if (t == 0.0f) {
        // Greedy: argmax of raw logits (first occurrence wins).
#pragma unroll 1
        for (int it = 0; it < NITER; ++it) {
            int c = (it * TPB + tid) * 4;
            float4 x = *reinterpret_cast<const float4*>(p + c);
            float v[4] = {x.x, x.y, x.z, x.w};
#pragma unroll
            for (int k = 0; k < 4; ++k) {
                if (v[k] > best) { best = v[k]; bidx = seg * COLS + c + k; }
            }
        }
    } else {
        const float invT = 1.0f / t;
        const unsigned ibase = (unsigned)row * (unsigned)NV + (unsigned)(seg * COLS);
#pragma unroll 1
        for (int it = 0; it < NITER; ++it) {
            int c = (it * TPB + tid) * 4;
            float4 x = *reinterpret_cast<const float4*>(p + c);
            unsigned bits[4];
#pragma unroll
            for (int k = 0; k < 4; ++k)
                bits[k] = threefry_fold(ibase + (unsigned)(c + k), one, ks1r, ks2r);
            float xv[4] = {x.x, x.y, x.z, x.w};
#pragma unroll
            for (int k = 0; k < 4; ++k) {
                float g = gumbel32(bits[k]);
                float v = fmaf(xv[k], invT, g);
                if (v > best) { best = v; bidx = seg * COLS + c + k; }
            }
        }
    }

    // Block-level argmax reduction (tie-break: smaller index).
    __shared__ float sv[TPB];
    __shared__ int   si[TPB];
    __shared__ int   s_last;
    sv[tid] = best; si[tid] = bidx;
    __syncthreads();
#pragma unroll
    for (int s = TPB / 2; s > 0; s >>= 1) {
        if (tid < s) {
            float v2 = sv[tid + s]; int i2 = si[tid + s];
            float v1 = sv[tid];     int i1 = si[tid];
            if (v2 > v1 || (v2 == v1 && i2 < i1)) { sv[tid] = v2; si[tid] = i2; }
        }
        __syncthreads();
    }
    if (tid == 0) {
        g_pval[row * SEG + seg] = sv[0];
        g_pidx[row * SEG + seg] = si[0];
        __threadfence();
        int prev = atomicAdd(&g_cnt[row], 1);
        s_last = (prev == SEG - 1);
    }
    __syncthreads();

    // Last-arriving block for this row does the final 25-way argmax.
    if (s_last && tid < 32) {
        __threadfence();  // acquire: partials from all segments visible
        float v = __int_as_float(0xff800000);
        int   i = NV;
        if (tid < SEG) {
            v = g_pval[row * SEG + tid];
            i = g_pidx[row * SEG + tid];
        }
#pragma unroll
        for (int s = 16; s > 0; s >>= 1) {
            float v2 = __shfl_down_sync(0xFFFFFFFFu, v, s);
            int   i2 = __shfl_down_sync(0xFFFFFFFFu, i, s);
            if (v2 > v || (v2 == v && i2 < i)) { v = v2; i = i2; }
        }
        if (tid == 0) {
            out[row] = (float)i;   // float32 output: tokens < 2^24 exact
            g_cnt[row] = 0;        // reset for next graph replay
        }
    }
}

extern "C" void kernel_launch(void* const* d_in, const int* in_sizes, int n_in,
                              void* d_out, int out_size) {
    const float* logits = (const float*)d_in[0];   // [256, 128000] f32
    const float* temps  = (const float*)d_in[1];   // [256] f32
    (void)in_sizes; (void)n_in; (void)out_size;

    dim3 grid(SEG, NB);
    sampler_main<<<grid, TPB>>>(logits, temps, (float*)d_out);
}

// round 17
// speedup vs baseline: 1.2121x; 1.0048x over previous
#include <cuda_runtime.h>

// Sampler_8658654069314: temperature sampling, B=256 rows, V=128000 vocab.
// Greedy rows (t==0): argmax(logits). Sampled rows: Gumbel-max over logits/t
// with JAX threefry2x32 partitionable-mode PRNG, key (0, 42), fold out0^out1.
// Output dtype is float32 (token values < 2^24, exactly representable).
//
// R16: pipe-balance via single-register IMAD, not IMAD.WIDE (R15 showed wide
// ops cost ~2 issue slots). Every threefry add 'x0 += x1' becomes
// mad.lo.u32(x1, one, x0) on the FMA pipe, with 'one' loaded from __constant__
// so ptxas cannot strength-reduce it back to IADD3 (alu). Rotates stay SHF.
// Per round: IMAD(fma) + SHF(alu) + LOP3(alu) -> alu ~50/elem, fma ~50/elem.
// Fused single-kernel final reduce (validated in R15) retained.

#define NB   256
#define NV   128000
#define SEG  25
#define COLS (NV / SEG)            // 5120
#define TPB  256
#define NITER (COLS / (TPB * 4))   // 5 float4 iterations per thread

// Deterministic partial-argmax scratch (no device allocation allowed).
__device__ float g_pval[NB * SEG];
__device__ int   g_pidx[NB * SEG];
__device__ int   g_cnt[NB];        // zero-init; last block resets to 0

// Opaque 1: forces integer adds onto the FMA pipe as IMAD.
__constant__ unsigned c_one = 1u;

// a + b on the FMA pipe: mad.lo.u32(a, one, b). Single-register IMAD, rt=2.
__device__ __forceinline__ unsigned add_fma(unsigned a, unsigned b, unsigned one) {
    unsigned r;
    asm("mad.lo.u32 %0, %1, %2, %3;" : "=r"(r) : "r"(a), "r"(one), "r"(b));
    return r;
}

// threefry2x32, key = (0, 42), counter = (hi=0, lo=ctr), 20 rounds.
// Partitionable-mode 32-bit draw = out0 ^ out1.
// ks0 = 0, ks1 = 42, ks2 = 0x1BD11BDA ^ 42 = 0x1BD11BF0.
__device__ __forceinline__ unsigned threefry_fold(unsigned ctr, unsigned one,
                                                  unsigned ks1r, unsigned ks2r) {
    unsigned x0 = 0u;             // 0 + ks0
    unsigned x1 = ctr + 42u;      // ctr + ks1
    // Round: x0 += x1 (IMAD, fma pipe); x1 = rotl(x1,r) ^ x0 (SHF+LOP3, alu).
#define TF_R(r) { x0 = add_fma(x1, x0, one); \
                  x1 = __funnelshift_l(x1, x1, (r)) ^ x0; }
    TF_R(13) TF_R(15) TF_R(26) TF_R(6)
    x0 = add_fma(ks1r, x0, one); x1 += 0x1BD11BF0u + 1u;   // + ks2 + 1
    TF_R(17) TF_R(29) TF_R(16) TF_R(24)
    x0 = add_fma(ks2r, x0, one); x1 += 2u;                 // + ks0 + 2
    TF_R(13) TF_R(15) TF_R(26) TF_R(6)
    /* x0 += ks0 == 0 */         x1 += 42u + 3u;           // + ks1 + 3
    TF_R(17) TF_R(29) TF_R(16) TF_R(24)
    x0 = add_fma(ks1r, x0, one); x1 += 0x1BD11BF0u + 4u;   // + ks2 + 4
    TF_R(13) TF_R(15) TF_R(26) TF_R(6)
    x0 = add_fma(ks2r, x0, one); x1 += 5u;                 // + ks0 + 5
#undef TF_R
    return x0 ^ x1;
}

// Accurate log(u) for u in [2^-126, 1). Cephes-style: relative-accurate near
// u->1 (critical: -log(u) can be ~1e-7 for the Gumbel winner). Branch-free,
// independent of --use_fast_math. Mostly FFMA (fma pipe).
__device__ __forceinline__ float log_accurate(float u) {
    int   ib = __float_as_int(u);
    int   e  = (ib >> 23) - 126;                              // u = m * 2^e, m in [0.5,1)
    float m  = __int_as_float((ib & 0x007FFFFF) | 0x3F000000);
    bool  sm = m < 0.70710678f;
    float x  = sm ? fmaf(2.0f, m, -1.0f) : (m - 1.0f);        // exact in both branches
    e -= (int)sm;

    float z = x * x;
    float p =              7.0376836292e-2f;
    p = fmaf(p, x, -1.1514610310e-1f);
    p = fmaf(p, x,  1.1676998740e-1f);
    p = fmaf(p, x, -1.2420140846e-1f);
    p = fmaf(p, x,  1.4249322787e-1f);
    p = fmaf(p, x, -1.6668057665e-1f);
    p = fmaf(p, x,  2.0000714765e-1f);
    p = fmaf(p, x, -2.4999993993e-1f);
    p = fmaf(p, x,  3.3333331174e-1f);
    float fe = (float)e;
    float y  = x * z * p;                     // x^3 * P(x)
    y = fmaf(fe, -2.12194440e-4f, y);         // + e * ln2_lo
    y = fmaf(-0.5f, z, y);                    // - x^2/2
    float r = x + y;
    r = fmaf(fe, 0.693359375f, r);            // + e * ln2_hi (exact product)
    return r;
}

__device__ __forceinline__ float gumbel32(unsigned bits) {
    // JAX uniform: u0 = bitcast(bits>>9 | 0x3f800000) - 1; u = max(u0, tiny)
    float u0 = __uint_as_float((bits >> 9) | 0x3F800000u) - 1.0f;
    float u  = fmaxf(u0, 1.17549435e-38f);
    float w  = -log_accurate(u);              // relative-accurate where it matters
    return -__logf(w);                        // MUFU.LG2 path: 4e-6 abs err, harmless
}

__global__ void __launch_bounds__(TPB)
sampler_main(const float* __restrict__ logits, const float* __restrict__ temps,
             float* __restrict__ out) {
    const int row = blockIdx.y;
    const int seg = blockIdx.x;
    const int tid = threadIdx.x;
    const float t = temps[row];
    const float* p = logits + (size_t)row * NV + (size_t)seg * COLS;

    const unsigned one  = c_one;          // opaque 1 (LDC, hoisted)
    const unsigned ks1r = 42u * one;      // keep in registers for add_fma
    const unsigned ks2r = 0x1BD11BF0u * one;

    float best = __int_as_float(0xff800000);  // -inf
    int   bidx = NV;

    if (t == 0.0f) {
        // Greedy: argmax of raw logits (first occurrence wins).
#pragma unroll 1
        for (int it = 0; it < NITER; ++it) {
            int c = (it * TPB + tid) * 4;
            float4 x = *reinterpret_cast<const float4*>(p + c);
            float v[4] = {x.x, x.y, x.z, x.w};
#pragma unroll
            for (int k = 0; k < 4; ++k) {
                if (v[k] > best) { best = v[k]; bidx = seg * COLS + c + k; }
            }
        }
    } else {
        const float invT = 1.0f / t;
        const unsigned ibase = (unsigned)row * (unsigned)NV + (unsigned)(seg * COLS);
#pragma unroll 1
        for (int it = 0; it < NITER; ++it) {
            int c = (it * TPB + tid) * 4;
            float4 x = *reinterpret_cast<const float4*>(p + c);
            unsigned bits[4];
#pragma unroll
            for (int k = 0; k < 4; ++k)
                bits[k] = threefry_fold(ibase + (unsigned)(c + k), one, ks1r, ks2r);
            float xv[4] = {x.x, x.y, x.z, x.w};
#pragma unroll
            for (int k = 0; k < 4; ++k) {
                float g = gumbel32(bits[k]);
                float v = fmaf(xv[k], invT, g);
                if (v > best) { best = v; bidx = seg * COLS + c + k; }
            }
        }
    }

    // Block-level argmax reduction (tie-break: smaller index).
    __shared__ float sv[TPB];
    __shared__ int   si[TPB];
    __shared__ int   s_last;
    sv[tid] = best; si[tid] = bidx;
    __syncthreads();
#pragma unroll
    for (int s = TPB / 2; s > 0; s >>= 1) {
        if (tid < s) {
            float v2 = sv[tid + s]; int i2 = si[tid + s];
            float v1 = sv[tid];     int i1 = si[tid];
            if (v2 > v1 || (v2 == v1 && i2 < i1)) { sv[tid] = v2; si[tid] = i2; }
        }
        __syncthreads();
    }
    if (tid == 0) {
        g_pval[row * SEG + seg] = sv[0];
        g_pidx[row * SEG + seg] = si[0];
        __threadfence();
        int prev = atomicAdd(&g_cnt[row], 1);
        s_last = (prev == SEG - 1);
    }
    __syncthreads();

    // Last-arriving block for this row does the final 25-way argmax.
    if (s_last && tid < 32) {
        __threadfence();  // acquire: partials from all segments visible
        float v = __int_as_float(0xff800000);
        int   i = NV;
        if (tid < SEG) {
            v = g_pval[row * SEG + tid];
            i = g_pidx[row * SEG + tid];
        }
#pragma unroll
        for (int s = 16; s > 0; s >>= 1) {
            float v2 = __shfl_down_sync(0xFFFFFFFFu, v, s);
            int   i2 = __shfl_down_sync(0xFFFFFFFFu, i, s);
            if (v2 > v || (v2 == v && i2 < i)) { v = v2; i = i2; }
        }
        if (tid == 0) {
            out[row] = (float)i;   // float32 output: tokens < 2^24 exact
            g_cnt[row] = 0;        // reset for next graph replay
        }
    }
}

extern "C" void kernel_launch(void* const* d_in, const int* in_sizes, int n_in,
                              void* d_out, int out_size) {
    const float* logits = (const float*)d_in[0];   // [256, 128000] f32
    const float* temps  = (const float*)d_in[1];   // [256] f32
    (void)in_sizes; (void)n_in; (void)out_size;

    dim3 grid(SEG, NB);
    sampler_main<<<grid, TPB>>>(logits, temps, (float*)d_out);
}